// round 8
// baseline (speedup 1.0000x reference)
#include <cuda_runtime.h>
#include <cuda_bf16.h>
#include <cstddef>

#define BB      4
#define SS      2048
#define D_IN    1024
#define D_MODEL 1024
#define NH      16
#define HD      64
#define MROWS   (BB * SS)          // 8192
#define QKV_N   (3 * D_MODEL)      // 3072

// Scratch (__device__ globals; no allocation allowed)
__device__ float g_x[(size_t)MROWS * D_IN];        // rounded + perm16 x
__device__ float g_wqkv[(size_t)D_IN * QKV_N];     // rounded W_qkv^T [3072][1024] perm16
__device__ float g_wo[(size_t)D_MODEL * D_MODEL];  // rounded W_o^T   [1024][1024] perm16
__device__ float g_qkv[(size_t)MROWS * QKV_N];     // rounded qkv (natural)
__device__ float g_vr[(size_t)MROWS * D_MODEL];    // rounded values, perm16
__device__ float g_vals[(size_t)MROWS * D_MODEL];  // fallback for values
__device__ int   g_mnz;                            // mask-nonzero flag

// ---------------------------------------------------------------------------
// helpers
// ---------------------------------------------------------------------------
__device__ __forceinline__ unsigned f2tf(float f) {
    unsigned r;
    asm("cvt.rna.tf32.f32 %0, %1;" : "=r"(r) : "f"(f));
    return r;
}

__device__ __forceinline__ void mma1688(float* c, const unsigned* a, const unsigned* b) {
    asm volatile(
        "mma.sync.aligned.m16n8k8.row.col.f32.tf32.tf32.f32 "
        "{%0,%1,%2,%3}, {%4,%5,%6,%7}, {%8,%9}, {%0,%1,%2,%3};"
        : "+f"(c[0]), "+f"(c[1]), "+f"(c[2]), "+f"(c[3])
        : "r"(a[0]), "r"(a[1]), "r"(a[2]), "r"(a[3]), "r"(b[0]), "r"(b[1]));
}

__device__ __forceinline__ void cpa16(unsigned dst, const void* src) {
    asm volatile("cp.async.cg.shared.global [%0], [%1], 16;\n" :: "r"(dst), "l"(src));
}
#define CP_COMMIT() asm volatile("cp.async.commit_group;\n")
#define CP_WAIT1()  asm volatile("cp.async.wait_group 1;\n")
#define CP_WAIT0()  asm volatile("cp.async.wait_group 0;\n")

// ---------------------------------------------------------------------------
// pre-pass kernels
// perm16: within each 16-float k-group, logical k -> ((k&3)<<2) | ((k>>2)&3)
// (makes the 4 words of an mma fragment kk-pair one contiguous 16B chunk)
// ---------------------------------------------------------------------------
__global__ void round_perm16_kernel(const float4* __restrict__ in,
                                    float* __restrict__ out, int n4) {
    int i = blockIdx.x * blockDim.x + threadIdx.x;
    int st = gridDim.x * blockDim.x;
    for (; i < n4; i += st) {
        float4 v = in[i];
        int base = (i & ~3) * 4;          // 16-group start
        int sub  = i & 3;                 // which float4 in the group
        float vals[4] = { v.x, v.y, v.z, v.w };
#pragma unroll
        for (int j = 0; j < 4; j++)
            out[base + (j << 2) + sub] = __uint_as_float(f2tf(vals[j]));
    }
}

// out[c][perm16(r)] = tf32_round(in[r][c]);  in is R x C
__global__ void transpose_round16_kernel(const float* __restrict__ in,
                                         float* __restrict__ out, int R, int C) {
    __shared__ float t[32][33];
    int r0 = blockIdx.y * 32, c0 = blockIdx.x * 32;
#pragma unroll
    for (int i = threadIdx.y; i < 32; i += 8)
        t[i][threadIdx.x] = in[(size_t)(r0 + i) * C + c0 + threadIdx.x];
    __syncthreads();
#pragma unroll
    for (int i = threadIdx.y; i < 32; i += 8) {
        int k  = r0 + threadIdx.x;
        int kb = k & ~15, ko = k & 15;
        int kp = kb + (((ko & 3) << 2) | ((ko >> 2) & 3));
        out[(size_t)(c0 + i) * R + kp] = __uint_as_float(f2tf(t[threadIdx.x][i]));
    }
}

__global__ void reset_flag_kernel(int* f) { *f = 0; }

__global__ void mask_scan_kernel(const float4* __restrict__ m, int n4, int* flag) {
    int i = blockIdx.x * blockDim.x + threadIdx.x;
    int st = gridDim.x * blockDim.x;
    int any = 0;
    for (; i < n4; i += st) {
        float4 v = m[i];
        any |= (v.x != 0.f) | (v.y != 0.f) | (v.z != 0.f) | (v.w != 0.f);
    }
    any = __syncthreads_or(any);
    if (threadIdx.x == 0 && any) atomicOr(flag, 1);
}

// ---------------------------------------------------------------------------
// TF32 GEMM + bias: C[M,N] = A[M,K] @ BT[N,K]^T + bias[N]
// A and BT pre-rounded + perm16 k-interleaved. CTA 128x128x32, 8 warps,
// warp 64x32, 3-stage cp.async. ALL fragment loads are LDS.128:
// per 32-k stage per warp: 24 LDS.128 + 64 HMMA (was 64 LDS + 64 HMMA).
// Swizzle: chunk ^= ((row&1)<<2)|((row>>1)&3) — conflict-free loads+stores.
// roundOut=1: tf32-round output (qkv, natural layout).
// ---------------------------------------------------------------------------
#define GEMM_STAGE_BYTES 32768                      // 16KB A + 16KB B
#define GEMM_SMEM_BYTES  (3 * GEMM_STAGE_BYTES)     // 96 KB

__global__ __launch_bounds__(256, 2) void gemm_tf32_pipe(
    const float* __restrict__ A, const float* __restrict__ BT,
    const float* __restrict__ bias, float* __restrict__ C,
    int M, int N, int K, int roundOut)
{
    extern __shared__ float gsm[];
    unsigned sbase = (unsigned)__cvta_generic_to_shared(gsm);

    const int tid  = threadIdx.x;
    const int wid  = tid >> 5;
    const int lane = tid & 31;
    const int grp  = lane >> 2;
    const int qd   = lane & 3;
    const int wm   = (wid >> 2) * 64;
    const int wn   = (wid & 3) * 32;
    const int m0   = blockIdx.y * 128;
    const int n0   = blockIdx.x * 128;
    // lane-constant read swizzle (rows in a fragment differ by 8/16 -> same value)
    const int sz   = ((grp & 1) << 2) | ((grp >> 1) & 3);

    float acc[4][4][4];
#pragma unroll
    for (int im = 0; im < 4; im++)
#pragma unroll
        for (int jn = 0; jn < 4; jn++)
#pragma unroll
            for (int c = 0; c < 4; c++) acc[im][jn][c] = 0.f;

#define G_ISSUE(t, stg) do {                                                  \
    unsigned sa  = sbase + (stg) * GEMM_STAGE_BYTES;                          \
    unsigned sbb = sa + 16384u;                                               \
    const float* gA = A  + (size_t)m0 * K + (size_t)(t) * 32;                 \
    const float* gB = BT + (size_t)n0 * K + (size_t)(t) * 32;                 \
    _Pragma("unroll")                                                         \
    for (int i = 0; i < 4; i++) {                                             \
        int idx = tid + i * 256; int row = idx >> 3; int kg = idx & 7;        \
        int swr = ((row & 1) << 2) | ((row >> 1) & 3);                        \
        unsigned off = (unsigned)(row * 128 + ((kg ^ swr) << 4));             \
        cpa16(sa  + off, gA + (size_t)row * K + kg * 4);                      \
        cpa16(sbb + off, gB + (size_t)row * K + kg * 4);                      \
    }                                                                         \
    CP_COMMIT();                                                              \
} while (0)

    const int T = K >> 5;
    G_ISSUE(0, 0);
    G_ISSUE(1, 1);
    CP_WAIT1();
    __syncthreads();

    int stg = 0, nstg = 2;
    for (int t = 0; t < T; t++) {
        if (t + 2 < T) G_ISSUE(t + 2, nstg);

        const unsigned* ua = (const unsigned*)gsm + stg * 8192;
        const unsigned* ub = ua + 4096;
#pragma unroll
        for (int g = 0; g < 2; g++) {
            const int ch = (((g << 2) | qd) ^ sz) << 2;   // word offset of chunk
            uint4 xa[4], ya[4];
#pragma unroll
            for (int im = 0; im < 4; im++) {
                int r = wm + im * 16 + grp;
                xa[im] = *(const uint4*)(ua + r * 32 + ch);
                ya[im] = *(const uint4*)(ua + (r + 8) * 32 + ch);
            }
#pragma unroll
            for (int jn = 0; jn < 4; jn++) {
                int cl = wn + jn * 8 + grp;
                uint4 bq = *(const uint4*)(ub + cl * 32 + ch);
                unsigned b0[2] = { bq.x, bq.y };
                unsigned b1[2] = { bq.z, bq.w };
#pragma unroll
                for (int im = 0; im < 4; im++) {
                    unsigned a0[4] = { xa[im].x, ya[im].x, xa[im].y, ya[im].y };
                    mma1688(acc[im][jn], a0, b0);
                }
#pragma unroll
                for (int im = 0; im < 4; im++) {
                    unsigned a1[4] = { xa[im].z, ya[im].z, xa[im].w, ya[im].w };
                    mma1688(acc[im][jn], a1, b1);
                }
            }
        }

        if (t + 2 < T) CP_WAIT1(); else CP_WAIT0();
        __syncthreads();
        stg  = (stg  + 1 == 3) ? 0 : stg  + 1;
        nstg = (nstg + 1 == 3) ? 0 : nstg + 1;
    }
#undef G_ISSUE

    // epilogue (natural N layout)
#pragma unroll
    for (int im = 0; im < 4; im++) {
        int rA = m0 + wm + im * 16 + grp;
        int rB = rA + 8;
#pragma unroll
        for (int jn = 0; jn < 4; jn++) {
            int col = n0 + wn + jn * 8 + 2 * qd;
            float bx = bias[col], by = bias[col + 1];
            float2 oA = { acc[im][jn][0] + bx, acc[im][jn][1] + by };
            float2 oB = { acc[im][jn][2] + bx, acc[im][jn][3] + by };
            if (roundOut) {
                oA.x = __uint_as_float(f2tf(oA.x));
                oA.y = __uint_as_float(f2tf(oA.y));
                oB.x = __uint_as_float(f2tf(oB.x));
                oB.y = __uint_as_float(f2tf(oB.y));
            }
            *(float2*)&C[(size_t)rA * N + col] = oA;
            *(float2*)&C[(size_t)rB * N + col] = oB;
        }
    }
}

// ---------------------------------------------------------------------------
// Flash attention, tf32 mma (round-6 math, unchanged). 256 threads,
// 8 warps x 16 q-rows = 128 q-rows/CTA, double-buffered K/V, Q in registers.
// Writes vout (fp32, natural) and vr (tf32-rounded, perm16 for GEMM2).
// ---------------------------------------------------------------------------
#define ATT_SMEM_BYTES 98304

__global__ __launch_bounds__(256, 2) void attn_pipe(
    const float* __restrict__ qkv,
    const float* __restrict__ mask,
    const int* __restrict__ mnz,
    float* __restrict__ vout,
    float* __restrict__ vr)
{
    extern __shared__ float sm[];
    unsigned sbase = (unsigned)__cvta_generic_to_shared(sm);
    const unsigned* usm = (const unsigned*)sm;
    unsigned* upw = (unsigned*)sm + 16384;          // P region (128x64 words)

    const int tid  = threadIdx.x;
    const int wid  = tid >> 5;
    const int lane = tid & 31;
    const int grp  = lane >> 2;
    const int qd   = lane & 3;
    const int q0   = blockIdx.x * 128;
    const int bh   = blockIdx.y;
    const int b    = bh >> 4, h = bh & 15;
    const float scale = 0.125f;

    const int rA = wid * 16 + grp;
    const int rB = rA + 8;

    const float* qbase = qkv + (size_t)b * SS * QKV_N + h * 192;
    const float* kbase = qbase + 64;
    const float* vbase = qbase + 128;
    const int use_mask = *mnz;

    unsigned qa[8][4];
    {
        const unsigned* qAp = (const unsigned*)qbase + (size_t)(q0 + rA) * QKV_N;
        const unsigned* qBp = (const unsigned*)qbase + (size_t)(q0 + rB) * QKV_N;
#pragma unroll
        for (int kk = 0; kk < 8; kk++) {
            qa[kk][0] = qAp[kk * 8 + qd];
            qa[kk][1] = qBp[kk * 8 + qd];
            qa[kk][2] = qAp[kk * 8 + qd + 4];
            qa[kk][3] = qBp[kk * 8 + qd + 4];
        }
    }

    float o[8][4];
#pragma unroll
    for (int jn = 0; jn < 8; jn++)
#pragma unroll
        for (int c = 0; c < 4; c++) o[jn][c] = 0.f;
    float mA = -1e30f, mB = -1e30f, lA = 0.f, lB = 0.f;

    const float* mrowA = mask + (size_t)(q0 + rA) * SS;
    const float* mrowB = mask + (size_t)(q0 + rB) * SS;

#define A_ISSUE(t) do {                                                       \
    int st = (t) & 1;                                                         \
    unsigned ks = sbase + (unsigned)st * 16384;                               \
    unsigned vs = sbase + 32768 + (unsigned)st * 16384;                       \
    const float* gK = kbase + (size_t)(t) * 64 * QKV_N;                       \
    const float* gV = vbase + (size_t)(t) * 64 * QKV_N;                       \
    _Pragma("unroll")                                                         \
    for (int i = 0; i < 4; i++) {                                             \
        int g = tid + i * 256; int row = g >> 4; int kg = g & 15;             \
        cpa16(ks + (unsigned)(row * 64 + ((kg ^ (row & 7)) << 2)) * 4,        \
              gK + (size_t)row * QKV_N + kg * 4);                             \
        cpa16(vs + (unsigned)(row * 64 + ((kg ^ ((row & 3) << 1)) << 2)) * 4, \
              gV + (size_t)row * QKV_N + kg * 4);                             \
    }                                                                         \
    CP_COMMIT();                                                              \
} while (0)

    A_ISSUE(0);

    for (int t = 0; t < SS / 64; t++) {
        if (t + 1 < SS / 64) { A_ISSUE(t + 1); CP_WAIT1(); }
        else CP_WAIT0();
        __syncthreads();

        const unsigned* uk = usm + (t & 1) * 4096;
        const unsigned* uv = usm + 8192 + (t & 1) * 4096;

        float s[8][4];
#pragma unroll
        for (int jn = 0; jn < 8; jn++)
#pragma unroll
            for (int c = 0; c < 4; c++) s[jn][c] = 0.f;

#pragma unroll
        for (int kk = 0; kk < 8; kk++) {
            int s0 = ((kk * 2) ^ grp) << 2;
            int s1 = ((kk * 2 + 1) ^ grp) << 2;
#pragma unroll
            for (int jn = 0; jn < 8; jn++) {
                int cl = jn * 8 + grp;
                unsigned bf[2];
                bf[0] = uk[cl * 64 + s0 + qd];
                bf[1] = uk[cl * 64 + s1 + qd];
                mma1688(s[jn], qa[kk], bf);
            }
        }

        if (use_mask) {
#pragma unroll
            for (int jn = 0; jn < 8; jn++) {
                int col = t * 64 + jn * 8 + 2 * qd;
                float2 mk0 = *(const float2*)&mrowA[col];
                float2 mk1 = *(const float2*)&mrowB[col];
                s[jn][0] = fmaf(s[jn][0], scale, mk0.x);
                s[jn][1] = fmaf(s[jn][1], scale, mk0.y);
                s[jn][2] = fmaf(s[jn][2], scale, mk1.x);
                s[jn][3] = fmaf(s[jn][3], scale, mk1.y);
            }
        } else {
#pragma unroll
            for (int jn = 0; jn < 8; jn++)
#pragma unroll
                for (int c = 0; c < 4; c++) s[jn][c] *= scale;
        }

        float pA = -1e30f, pB = -1e30f;
#pragma unroll
        for (int jn = 0; jn < 8; jn++) {
            pA = fmaxf(pA, fmaxf(s[jn][0], s[jn][1]));
            pB = fmaxf(pB, fmaxf(s[jn][2], s[jn][3]));
        }
        pA = fmaxf(pA, __shfl_xor_sync(0xffffffffu, pA, 1));
        pA = fmaxf(pA, __shfl_xor_sync(0xffffffffu, pA, 2));
        pB = fmaxf(pB, __shfl_xor_sync(0xffffffffu, pB, 1));
        pB = fmaxf(pB, __shfl_xor_sync(0xffffffffu, pB, 2));

        float nA = fmaxf(mA, pA), nB = fmaxf(mB, pB);
        float cA = __expf(mA - nA), cB = __expf(mB - nB);
        mA = nA; mB = nB;

        float sA = 0.f, sB = 0.f;
#pragma unroll
        for (int jn = 0; jn < 8; jn++) {
            s[jn][0] = __expf(s[jn][0] - nA);
            s[jn][1] = __expf(s[jn][1] - nA);
            s[jn][2] = __expf(s[jn][2] - nB);
            s[jn][3] = __expf(s[jn][3] - nB);
            sA += s[jn][0] + s[jn][1];
            sB += s[jn][2] + s[jn][3];
        }
        sA += __shfl_xor_sync(0xffffffffu, sA, 1);
        sA += __shfl_xor_sync(0xffffffffu, sA, 2);
        sB += __shfl_xor_sync(0xffffffffu, sB, 1);
        sB += __shfl_xor_sync(0xffffffffu, sB, 2);
        lA = lA * cA + sA;
        lB = lB * cB + sB;
#pragma unroll
        for (int jn = 0; jn < 8; jn++) {
            o[jn][0] *= cA; o[jn][1] *= cA;
            o[jn][2] *= cB; o[jn][3] *= cB;
        }

#pragma unroll
        for (int jn = 0; jn < 8; jn++) {
            int kg   = jn * 2 + (qd >> 1);
            int colw = ((kg ^ grp) << 2) + 2 * (qd & 1);
            uint2 wA = { f2tf(s[jn][0]), f2tf(s[jn][1]) };
            uint2 wB = { f2tf(s[jn][2]), f2tf(s[jn][3]) };
            *(uint2*)(upw + rA * 64 + colw) = wA;
            *(uint2*)(upw + rB * 64 + colw) = wB;
        }
        __syncwarp();

#pragma unroll
        for (int kk = 0; kk < 8; kk++) {
            int s0 = ((kk * 2) ^ grp) << 2;
            int s1 = ((kk * 2 + 1) ^ grp) << 2;
            unsigned pa[4];
            pa[0] = upw[rA * 64 + s0 + qd];
            pa[1] = upw[rB * 64 + s0 + qd];
            pa[2] = upw[rA * 64 + s1 + qd];
            pa[3] = upw[rB * 64 + s1 + qd];
            int rowv0 = (kk * 8 + qd) * 64;
            int rowv1 = (kk * 8 + qd + 4) * 64;
            int sw = qd << 1;
#pragma unroll
            for (int jn = 0; jn < 8; jn++) {
                int d  = jn * 8 + grp;
                int col = (((d >> 2) ^ sw) << 2) + (d & 3);
                unsigned bf[2];
                bf[0] = uv[rowv0 + col];
                bf[1] = uv[rowv1 + col];
                mma1688(o[jn], pa, bf);
            }
        }
        __syncthreads();
    }
#undef A_ISSUE

    // normalize + write values (fp32, natural) and rounded perm16 copy
    float iA = 1.f / lA, iB = 1.f / lB;
    size_t gRA = (size_t)b * SS + q0 + rA;
    size_t gRB = (size_t)b * SS + q0 + rB;
#pragma unroll
    for (int jn = 0; jn < 8; jn++) {
        int col = h * HD + jn * 8 + 2 * qd;
        float2 oA = { o[jn][0] * iA, o[jn][1] * iA };
        float2 oB = { o[jn][2] * iB, o[jn][3] * iB };
        *(float2*)&vout[gRA * D_MODEL + col] = oA;
        *(float2*)&vout[gRB * D_MODEL + col] = oB;
        // perm16 positions for GEMM2's A operand
        int base16 = col & ~15;
        int o0 = col & 15, o1 = o0 + 1;
        int p0 = ((o0 & 3) << 2) | ((o0 >> 2) & 3);
        int p1 = ((o1 & 3) << 2) | ((o1 >> 2) & 3);
        vr[gRA * D_MODEL + base16 + p0] = __uint_as_float(f2tf(oA.x));
        vr[gRA * D_MODEL + base16 + p1] = __uint_as_float(f2tf(oA.y));
        vr[gRB * D_MODEL + base16 + p0] = __uint_as_float(f2tf(oB.x));
        vr[gRB * D_MODEL + base16 + p1] = __uint_as_float(f2tf(oB.y));
    }
}

// ---------------------------------------------------------------------------
// Launch
// ---------------------------------------------------------------------------
extern "C" void kernel_launch(void* const* d_in, const int* in_sizes, int n_in,
                              void* d_out, int out_size)
{
    const float* x     = (const float*)d_in[0];
    const float* mask  = (const float*)d_in[1];
    const float* W_qkv = (const float*)d_in[2];
    const float* b_qkv = (const float*)d_in[3];
    const float* W_o   = (const float*)d_in[4];
    const float* b_o   = (const float*)d_in[5];
    float* out = (float*)d_out;

    float *gx, *gwqkvT, *gwoT, *qkv_buf, *gvr, *vals_fb;
    int* flag;
    cudaGetSymbolAddress((void**)&gx, g_x);
    cudaGetSymbolAddress((void**)&gwqkvT, g_wqkv);
    cudaGetSymbolAddress((void**)&gwoT, g_wo);
    cudaGetSymbolAddress((void**)&qkv_buf, g_qkv);
    cudaGetSymbolAddress((void**)&gvr, g_vr);
    cudaGetSymbolAddress((void**)&vals_fb, g_vals);
    cudaGetSymbolAddress((void**)&flag, g_mnz);

    const size_t half = (size_t)MROWS * D_MODEL;
    float* vbuf = ((size_t)out_size >= 2 * half) ? (out + half) : vals_fb;

    static bool attr_done = false;
    if (!attr_done) {
        cudaFuncSetAttribute(gemm_tf32_pipe,
                             cudaFuncAttributeMaxDynamicSharedMemorySize,
                             GEMM_SMEM_BYTES);
        cudaFuncSetAttribute(attn_pipe,
                             cudaFuncAttributeMaxDynamicSharedMemorySize,
                             ATT_SMEM_BYTES);
        attr_done = true;
    }

    // prepass: mask flag; round+perm16 x; transpose+round+perm16 weights
    reset_flag_kernel<<<1, 1>>>(flag);
    mask_scan_kernel<<<1024, 256>>>((const float4*)mask, SS * SS / 4, flag);
    round_perm16_kernel<<<2048, 256>>>((const float4*)x, gx, MROWS * D_IN / 4);
    {
        dim3 blk(32, 8);
        transpose_round16_kernel<<<dim3(QKV_N / 32, D_IN / 32), blk>>>(
            W_qkv, gwqkvT, D_IN, QKV_N);
        transpose_round16_kernel<<<dim3(D_MODEL / 32, D_MODEL / 32), blk>>>(
            W_o, gwoT, D_MODEL, D_MODEL);
    }

    // 1) qkv = x @ W_qkv + b_qkv  (rounded natural output)
    {
        dim3 grid(QKV_N / 128, MROWS / 128);   // 24 x 64
        gemm_tf32_pipe<<<grid, 256, GEMM_SMEM_BYTES>>>(
            gx, gwqkvT, b_qkv, qkv_buf, MROWS, QKV_N, D_IN, 1);
    }

    // 2) attention -> values (fp32) + rounded perm16 copy
    {
        dim3 grid(SS / 128, BB * NH);          // 16 x 64
        attn_pipe<<<grid, 256, ATT_SMEM_BYTES>>>(qkv_buf, mask, flag, vbuf, gvr);
    }

    // 3) out = values @ W_o + b_o
    {
        dim3 grid(D_MODEL / 128, MROWS / 128); // 8 x 64
        gemm_tf32_pipe<<<grid, 256, GEMM_SMEM_BYTES>>>(
            gvr, gwoT, b_o, out, MROWS, D_MODEL, D_MODEL, 0);
    }
}